// round 2
// baseline (speedup 1.0000x reference)
#include <cuda_runtime.h>
#include <math.h>

// ---------------- problem constants ----------------
constexpr int B_  = 512;
constexpr int T_  = 200;
constexpr int D_  = 64;
constexpr int H_  = 256;
constexpr int BT  = B_ * T_;        // 102400 rows
constexpr int HT  = H_ * T_;        // 51200 flat dim
constexpr int C1_ = 1024;
constexpr int C2_ = 256;
constexpr int C3_ = 10;
constexpr int R1_ = 1024;
constexpr int G3  = 768;            // packed gates: i,g,o (forget gate dead, c0=0)

// output regions in d_out (float)
constexpr size_t OUT_TOTAL_OFF = 0;                       // [512,200,256]
constexpr size_t OUT_CLASS_OFF = (size_t)BT * H_;         // 26214400, [512,10]
constexpr size_t OUT_REG_OFF   = OUT_CLASS_OFF + (size_t)B_ * C3_; // [512,200]

// ---------------- device scratch (no allocs allowed) ----------------
__device__ float g_Wsel0[G3 * D_];            // packed i,g,o rows of W_ih0
__device__ float g_Wsel1[G3 * H_];            // packed i,g,o rows of W_ih1
__device__ float g_bsel0[G3];
__device__ float g_bsel1[G3];
__device__ float g_h0[(size_t)BT * H_];       // 105 MB
__device__ float g_gates[(size_t)BT * G3];    // 315 MB
__device__ float g_part[8 * 512 * 1024];      // split-K partials, 16.8 MB
__device__ float g_c1[B_ * C1_];
__device__ float g_c2[B_ * C2_];
__device__ float g_r [B_ * R1_];

// ---------------- kernels ----------------

// Pack gate rows {i:[0,256), g:[512,768), o:[768,1024)} of W_ih into [768,Kd],
// and bsel = b_ih + b_hh at the same rows.
__global__ void make_wsel(const float* __restrict__ W, const float* __restrict__ bih,
                          const float* __restrict__ bhh, float* __restrict__ Wsel,
                          float* __restrict__ bsel, int Kd)
{
    int idx = blockIdx.x * blockDim.x + threadIdx.x;
    int total = G3 * Kd;
    if (idx < total) {
        int j = idx / Kd;
        int c = idx - j * Kd;
        int src = j + ((j >= 256) ? 256 : 0);
        Wsel[idx] = W[src * Kd + c];
    }
    if (idx < G3) {
        int src = idx + ((idx >= 256) ? 256 : 0);
        bsel[idx] = bih[src] + bhh[src];
    }
}

// Generic C[M,N] (+=split) = A[M,K] * B[N,K]^T, fp32.
// Tiles: 128x128x8, 256 threads, 8x8 per thread.
// Requirements: M % 128 == 0, K-slice % 8 == 0, rows 16B-aligned (K % 4 == 0).
// N may be ragged (guarded). grid = (ceil(N/128), M/128, S); kSlice = K/S.
// Output written to C + z*M*N (partials when S>1).
__global__ void __launch_bounds__(256, 2)
sgemm_nt(const float* __restrict__ A, const float* __restrict__ B,
         float* __restrict__ C, int M, int N, int K, int kSlice)
{
    constexpr int BM = 128, BN = 128, BK = 8;
    __shared__ float As[BK][BM];
    __shared__ float Bs[BK][BN];

    const int tid   = threadIdx.x;
    const int mBase = blockIdx.y * BM;
    const int nBase = blockIdx.x * BN;
    const int z     = blockIdx.z;
    const int kBeg  = z * kSlice;
    const int kEnd  = kBeg + kSlice;

    // loader mapping: 256 threads load 128 rows x 8 cols as float4
    const int lr = tid >> 1;          // 0..127
    const int lc = (tid & 1) * 4;     // 0 or 4

    // compute mapping: 16x16 thread grid, 8x8 tile each
    const int tr = (tid >> 4) * 8;
    const int tc = (tid & 15) * 8;

    float acc[8][8];
#pragma unroll
    for (int i = 0; i < 8; i++)
#pragma unroll
        for (int j = 0; j < 8; j++) acc[i][j] = 0.f;

    const float* Aptr = A + (size_t)(mBase + lr) * K;
    const bool bvalid = (nBase + lr) < N;
    const float* Bptr = B + (bvalid ? (size_t)(nBase + lr) * K : 0);

    for (int k0 = kBeg; k0 < kEnd; k0 += BK) {
        float4 a4 = *reinterpret_cast<const float4*>(Aptr + k0 + lc);
        float4 b4 = make_float4(0.f, 0.f, 0.f, 0.f);
        if (bvalid) b4 = *reinterpret_cast<const float4*>(Bptr + k0 + lc);

        As[lc + 0][lr] = a4.x; As[lc + 1][lr] = a4.y;
        As[lc + 2][lr] = a4.z; As[lc + 3][lr] = a4.w;
        Bs[lc + 0][lr] = b4.x; Bs[lc + 1][lr] = b4.y;
        Bs[lc + 2][lr] = b4.z; Bs[lc + 3][lr] = b4.w;
        __syncthreads();

#pragma unroll
        for (int kk = 0; kk < BK; kk++) {
            float rm[8], rn[8];
#pragma unroll
            for (int i = 0; i < 8; i++) rm[i] = As[kk][tr + i];
#pragma unroll
            for (int j = 0; j < 8; j++) rn[j] = Bs[kk][tc + j];
#pragma unroll
            for (int i = 0; i < 8; i++)
#pragma unroll
                for (int j = 0; j < 8; j++) acc[i][j] = fmaf(rm[i], rn[j], acc[i][j]);
        }
        __syncthreads();
    }

    float* Cp = C + (size_t)z * M * N;
#pragma unroll
    for (int i = 0; i < 8; i++) {
        const size_t rowOff = (size_t)(mBase + tr + i) * N;
#pragma unroll
        for (int j = 0; j < 8; j++) {
            int col = nBase + tc + j;
            if (col < N) Cp[rowOff + col] = acc[i][j];
        }
    }
}

__device__ __forceinline__ float sigm(float x) { return 1.f / (1.f + expf(-x)); }

// gates[M,768] (i|g|o packed) + bsel -> h[M,256]
__global__ void lstm_gate(const float* __restrict__ gates, const float* __restrict__ bsel,
                          float* __restrict__ out, int M)
{
    int idx = blockIdx.x * blockDim.x + threadIdx.x;
    if (idx >= M * H_) return;
    int m = idx >> 8;
    int j = idx & 255;
    const float* gr = gates + (size_t)m * G3;
    float gi = gr[j]       + bsel[j];
    float gg = gr[256 + j] + bsel[256 + j];
    float go = gr[512 + j] + bsel[512 + j];
    float c = sigm(gi) * tanhf(gg);
    out[idx] = sigm(go) * tanhf(c);
}

// out[idx] = act( sum_s part[s][idx] + bias[idx%N] )
__global__ void reduce_bias_act(const float* __restrict__ part, int S, int MN, int N,
                                const float* __restrict__ bias, float* __restrict__ out,
                                int relu)
{
    int idx = blockIdx.x * blockDim.x + threadIdx.x;
    if (idx >= MN) return;
    float s = 0.f;
    for (int i = 0; i < S; i++) s += part[(size_t)i * MN + idx];
    s += bias[idx % N];
    if (relu) s = fmaxf(s, 0.f);
    out[idx] = s;
}

// tiny head: out[512,10] = c2[512,256] @ fc3_w[10,256]^T + b
__global__ void fc3_kernel(const float* __restrict__ x, const float* __restrict__ W,
                           const float* __restrict__ b, float* __restrict__ out)
{
    int idx = blockIdx.x * blockDim.x + threadIdx.x;
    if (idx >= B_ * C3_) return;
    int m = idx / C3_;
    int n = idx - m * C3_;
    const float* xr = x + m * C2_;
    const float* wr = W + n * C2_;
    float s = 0.f;
#pragma unroll 4
    for (int k = 0; k < C2_; k++) s = fmaf(xr[k], wr[k], s);
    out[idx] = s + b[n];
}

// ---------------- launch ----------------
extern "C" void kernel_launch(void* const* d_in, const int* in_sizes, int n_in,
                              void* d_out_v, int out_size)
{
    const float* x     = (const float*)d_in[0];
    const float* W_ih0 = (const float*)d_in[1];
    const float* b_ih0 = (const float*)d_in[2];
    const float* b_hh0 = (const float*)d_in[3];
    const float* W_ih1 = (const float*)d_in[4];
    const float* b_ih1 = (const float*)d_in[5];
    const float* b_hh1 = (const float*)d_in[6];
    const float* fc1_w = (const float*)d_in[7];
    const float* fc1_b = (const float*)d_in[8];
    const float* fc2_w = (const float*)d_in[9];
    const float* fc2_b = (const float*)d_in[10];
    const float* fc3_w = (const float*)d_in[11];
    const float* fc3_b = (const float*)d_in[12];
    const float* fc4_w = (const float*)d_in[13];
    const float* fc4_b = (const float*)d_in[14];
    const float* fc5_w = (const float*)d_in[15];
    const float* fc5_b = (const float*)d_in[16];
    float* d_out = (float*)d_out_v;

    float *Wsel0, *Wsel1, *bsel0, *bsel1, *h0, *gates, *part, *c1, *c2, *r;
    cudaGetSymbolAddress((void**)&Wsel0, g_Wsel0);
    cudaGetSymbolAddress((void**)&Wsel1, g_Wsel1);
    cudaGetSymbolAddress((void**)&bsel0, g_bsel0);
    cudaGetSymbolAddress((void**)&bsel1, g_bsel1);
    cudaGetSymbolAddress((void**)&h0,    g_h0);
    cudaGetSymbolAddress((void**)&gates, g_gates);
    cudaGetSymbolAddress((void**)&part,  g_part);
    cudaGetSymbolAddress((void**)&c1,    g_c1);
    cudaGetSymbolAddress((void**)&c2,    g_c2);
    cudaGetSymbolAddress((void**)&r,     g_r);

    // pack gate weights (skip forget gate)
    make_wsel<<<(G3 * D_ + 255) / 256, 256>>>(W_ih0, b_ih0, b_hh0, Wsel0, bsel0, D_);
    make_wsel<<<(G3 * H_ + 255) / 256, 256>>>(W_ih1, b_ih1, b_hh1, Wsel1, bsel1, H_);

    // LSTM layer 0: gates = x[102400,64] @ Wsel0[768,64]^T
    sgemm_nt<<<dim3(G3 / 128, BT / 128, 1), 256>>>(x, Wsel0, gates, BT, G3, D_, D_);
    lstm_gate<<<(BT * H_ + 255) / 256, 256>>>(gates, bsel0, h0, BT);

    // LSTM layer 1: gates = h0[102400,256] @ Wsel1[768,256]^T -> out_total
    sgemm_nt<<<dim3(G3 / 128, BT / 128, 1), 256>>>(h0, Wsel1, gates, BT, G3, H_, H_);
    lstm_gate<<<(BT * H_ + 255) / 256, 256>>>(gates, bsel1, d_out + OUT_TOTAL_OFF, BT);

    const float* flat = d_out + OUT_TOTAL_OFF;  // [512, 51200]

    // fc1 (split-K=8) + relu
    sgemm_nt<<<dim3(C1_ / 128, B_ / 128, 8), 256>>>(flat, fc1_w, part, B_, C1_, HT, HT / 8);
    reduce_bias_act<<<(B_ * C1_ + 255) / 256, 256>>>(part, 8, B_ * C1_, C1_, fc1_b, c1, 1);

    // fc2 (split-K=4) + relu
    sgemm_nt<<<dim3(C2_ / 128, B_ / 128, 4), 256>>>(c1, fc2_w, part, B_, C2_, C1_, C1_ / 4);
    reduce_bias_act<<<(B_ * C2_ + 255) / 256, 256>>>(part, 4, B_ * C2_, C2_, fc2_b, c2, 1);

    // fc3 -> class output
    fc3_kernel<<<(B_ * C3_ + 255) / 256, 256>>>(c2, fc3_w, fc3_b, d_out + OUT_CLASS_OFF);

    // fc4 (split-K=8) + relu
    sgemm_nt<<<dim3(R1_ / 128, B_ / 128, 8), 256>>>(flat, fc4_w, part, B_, R1_, HT, HT / 8);
    reduce_bias_act<<<(B_ * R1_ + 255) / 256, 256>>>(part, 8, B_ * R1_, R1_, fc4_b, r, 1);

    // fc5 (split-K=4, N=200 ragged) -> regression output
    sgemm_nt<<<dim3((T_ + 127) / 128, B_ / 128, 4), 256>>>(r, fc5_w, part, B_, T_, R1_, R1_ / 4);
    reduce_bias_act<<<(B_ * T_ + 255) / 256, 256>>>(part, 4, B_ * T_, T_, fc5_b,
                                                    d_out + OUT_REG_OFF, 0);
}

// round 5
// speedup vs baseline: 1.4988x; 1.4988x over previous
#include <cuda_runtime.h>
#include <cuda_bf16.h>
#include <math.h>
#include <stdint.h>

// ---------------- problem constants ----------------
constexpr int B_  = 512;
constexpr int T_  = 200;
constexpr int D_  = 64;
constexpr int H_  = 256;
constexpr int BT  = B_ * T_;        // 102400 rows
constexpr int HT  = H_ * T_;        // 51200 flat dim
constexpr int C1_ = 1024;
constexpr int C2_ = 256;
constexpr int C3_ = 10;
constexpr int R1_ = 1024;
constexpr int G3  = 768;            // packed gates i,g,o (forget gate dead, c0=0)

constexpr size_t OUT_TOTAL_OFF = 0;
constexpr size_t OUT_CLASS_OFF = (size_t)BT * H_;
constexpr size_t OUT_REG_OFF   = OUT_CLASS_OFF + (size_t)B_ * C3_;

// ---------------- device scratch ----------------
__device__ __nv_bfloat16 g_w0h[G3 * D_],  g_w0l[G3 * D_];
__device__ __nv_bfloat16 g_w1h[G3 * H_],  g_w1l[G3 * H_];
__device__ float g_bsel0[G3], g_bsel1[G3];
__device__ __nv_bfloat16 g_xh[(size_t)BT * D_],  g_xl[(size_t)BT * D_];
__device__ __nv_bfloat16 g_h0h[(size_t)BT * H_], g_h0l[(size_t)BT * H_];
__device__ __nv_bfloat16 g_fh [(size_t)BT * H_], g_fl [(size_t)BT * H_];
__device__ __nv_bfloat16 g_fc1h[(size_t)C1_ * HT], g_fc1l[(size_t)C1_ * HT];
__device__ __nv_bfloat16 g_fc4h[(size_t)R1_ * HT], g_fc4l[(size_t)R1_ * HT];
__device__ float g_gates[(size_t)BT * G3];        // 315 MB
__device__ float g_part[32 * 512 * 1024];         // split-K partials
__device__ float g_c1[B_ * C1_];
__device__ float g_c2[B_ * C2_];
__device__ float g_r [B_ * R1_];

// ---------------- PTX helpers (sm_80-compatible only) ----------------
__device__ __forceinline__ uint32_t smem_u32(const void* p) {
    uint32_t a;
    asm("{ .reg .u64 t; cvta.to.shared.u64 t, %1; cvt.u32.u64 %0, t; }" : "=r"(a) : "l"(p));
    return a;
}
__device__ __forceinline__ void cp_async16(uint32_t dst, const void* src) {
    asm volatile("cp.async.cg.shared.global [%0], [%1], 16;" :: "r"(dst), "l"(src));
}
#define CP_COMMIT() asm volatile("cp.async.commit_group;" ::: "memory")
template <int N>
__device__ __forceinline__ void cp_wait() {
    asm volatile("cp.async.wait_group %0;" :: "n"(N) : "memory");
}
__device__ __forceinline__ void ldsm_x4(uint32_t* r, uint32_t addr) {
    asm volatile("ldmatrix.sync.aligned.m8n8.x4.shared.b16 {%0,%1,%2,%3}, [%4];"
                 : "=r"(r[0]), "=r"(r[1]), "=r"(r[2]), "=r"(r[3]) : "r"(addr));
}
// non-transposed x2: B stored [N,K] row-major delivers the b-fragment layout
// (k = 2*(lane%4)+i, n = lane/4) directly.
__device__ __forceinline__ void ldsm_x2(uint32_t* r, uint32_t addr) {
    asm volatile("ldmatrix.sync.aligned.m8n8.x2.shared.b16 {%0,%1}, [%2];"
                 : "=r"(r[0]), "=r"(r[1]) : "r"(addr));
}
__device__ __forceinline__ void mma_bf16(float* c, const uint32_t* a, const uint32_t* b) {
    asm volatile("mma.sync.aligned.m16n8k16.row.col.f32.bf16.bf16.f32 "
                 "{%0,%1,%2,%3}, {%4,%5,%6,%7}, {%8,%9}, {%0,%1,%2,%3};"
                 : "+f"(c[0]), "+f"(c[1]), "+f"(c[2]), "+f"(c[3])
                 : "r"(a[0]), "r"(a[1]), "r"(a[2]), "r"(a[3]), "r"(b[0]), "r"(b[1]));
}

// ---------------- HMMA GEMM ----------------
// C[M,N] (+z slice) = sum_{pass in {hi*hi, hi*lo, lo*hi}} Ap[M,K] * Bp[N,K]^T
// over k in [z*kSlice, (z+1)*kSlice).  Tile 128x128x64, 8 warps.
// Requires M%128==0, N%128==0, kSlice%64==0.
constexpr int HM_PADE   = 72;                  // bf16 elems per smem row (64 + 8 pad)
constexpr int HM_ROWB   = HM_PADE * 2;         // 144 B row stride
constexpr int HM_TILE_B = 128 * HM_ROWB;       // 18432 B per operand tile
constexpr int HM_STAGE  = 2 * HM_TILE_B;       // A + B
constexpr int HM_SMEM   = 2 * HM_STAGE;        // double buffered = 73728 B

__global__ void __launch_bounds__(256, 2)
hm_gemm(const __nv_bfloat16* __restrict__ Ahi, const __nv_bfloat16* __restrict__ Alo,
        const __nv_bfloat16* __restrict__ Bhi, const __nv_bfloat16* __restrict__ Blo,
        float* __restrict__ C, int M, int N, int K, int kSlice)
{
    extern __shared__ __align__(128) char smem[];
    const uint32_t sb = smem_u32(smem);
    const int tid  = threadIdx.x;
    const int lane = tid & 31;
    const int warp = tid >> 5;
    const int wm   = warp >> 2;       // 0..1
    const int wn   = warp & 3;        // 0..3
    const int mBase = blockIdx.y * 128;
    const int nBase = blockIdx.x * 128;
    const int z     = blockIdx.z;
    const int kBeg  = z * kSlice;
    const int cpp   = kSlice >> 6;    // 64-wide chunks per pass
    const int NC    = 3 * cpp;

    // per-thread ldmatrix address components
    const int aRow = (lane & 7) + ((lane >> 3) & 1) * 8;   // within m16 tile
    const int aCol = (lane >> 4) * 8;                       // 0 or 8
    const int bRow = lane & 7;                              // within n8 tile
    const int bCol = ((lane >> 3) & 1) * 8;                 // k-half select

    // loader: 1024 16B-chunks per operand tile, 4 per thread
    int lrow[4], lc8[4];
#pragma unroll
    for (int t = 0; t < 4; t++) {
        int idx = tid + t * 256;
        lrow[t] = idx >> 3;           // 0..127
        lc8[t]  = idx & 7;            // 16B unit within 128B row
    }

    float acc[4][4][4];
#pragma unroll
    for (int mi = 0; mi < 4; mi++)
#pragma unroll
        for (int ni = 0; ni < 4; ni++)
#pragma unroll
            for (int q = 0; q < 4; q++) acc[mi][ni][q] = 0.f;

    auto prefetch = [&](int c, int s) {
        int pass = c / cpp;
        int kk = kBeg + (c - pass * cpp) * 64;
        const __nv_bfloat16* Ap = (pass == 2) ? Alo : Ahi;
        const __nv_bfloat16* Bp = (pass == 1) ? Blo : Bhi;
        uint32_t base = sb + s * HM_STAGE;
#pragma unroll
        for (int t = 0; t < 4; t++) {
            uint32_t dst = base + lrow[t] * HM_ROWB + lc8[t] * 16;
            const __nv_bfloat16* src = Ap + (size_t)(mBase + lrow[t]) * K + kk + lc8[t] * 8;
            cp_async16(dst, src);
        }
#pragma unroll
        for (int t = 0; t < 4; t++) {
            uint32_t dst = base + HM_TILE_B + lrow[t] * HM_ROWB + lc8[t] * 16;
            const __nv_bfloat16* src = Bp + (size_t)(nBase + lrow[t]) * K + kk + lc8[t] * 8;
            cp_async16(dst, src);
        }
        CP_COMMIT();
    };

    prefetch(0, 0);
    for (int c = 0; c < NC; c++) {
        if (c + 1 < NC) { prefetch(c + 1, (c + 1) & 1); cp_wait<1>(); }
        else            { cp_wait<0>(); }
        __syncthreads();

        uint32_t Ab = sb + (c & 1) * HM_STAGE;
        uint32_t Bb = Ab + HM_TILE_B;
#pragma unroll
        for (int ks = 0; ks < 4; ks++) {
            uint32_t af[4][4], bf[4][2];
#pragma unroll
            for (int mi = 0; mi < 4; mi++)
                ldsm_x4(af[mi], Ab + (wm * 64 + mi * 16 + aRow) * HM_ROWB + (ks * 16 + aCol) * 2);
#pragma unroll
            for (int ni = 0; ni < 4; ni++)
                ldsm_x2(bf[ni], Bb + (wn * 32 + ni * 8 + bRow) * HM_ROWB + (ks * 16 + bCol) * 2);
#pragma unroll
            for (int mi = 0; mi < 4; mi++)
#pragma unroll
                for (int ni = 0; ni < 4; ni++)
                    mma_bf16(acc[mi][ni], af[mi], bf[ni]);
        }
        __syncthreads();
    }

    // epilogue
    float* Cp = C + (size_t)z * M * N;
#pragma unroll
    for (int mi = 0; mi < 4; mi++) {
        int r0 = mBase + wm * 64 + mi * 16 + (lane >> 2);
#pragma unroll
        for (int ni = 0; ni < 4; ni++) {
            int col = nBase + wn * 32 + ni * 8 + (lane & 3) * 2;
            *reinterpret_cast<float2*>(&Cp[(size_t)r0 * N + col]) =
                make_float2(acc[mi][ni][0], acc[mi][ni][1]);
            *reinterpret_cast<float2*>(&Cp[(size_t)(r0 + 8) * N + col]) =
                make_float2(acc[mi][ni][2], acc[mi][ni][3]);
        }
    }
}

// ---------------- elementwise kernels ----------------
__device__ __forceinline__ void split1(float v, __nv_bfloat16& h, __nv_bfloat16& l) {
    h = __float2bfloat16(v);
    l = __float2bfloat16(v - __bfloat162float(h));
}

__global__ void split_f32(const float* __restrict__ src, __nv_bfloat16* __restrict__ hi,
                          __nv_bfloat16* __restrict__ lo, size_t n)
{
    size_t i = ((size_t)blockIdx.x * blockDim.x + threadIdx.x) * 4;
    if (i >= n) return;
    float4 v = *reinterpret_cast<const float4*>(src + i);
    __nv_bfloat16 h0, l0, h1, l1, h2, l2, h3, l3;
    split1(v.x, h0, l0); split1(v.y, h1, l1); split1(v.z, h2, l2); split1(v.w, h3, l3);
    hi[i] = h0; hi[i+1] = h1; hi[i+2] = h2; hi[i+3] = h3;
    lo[i] = l0; lo[i+1] = l1; lo[i+2] = l2; lo[i+3] = l3;
}

__global__ void make_wsel_split(const float* __restrict__ W, const float* __restrict__ bih,
                                const float* __restrict__ bhh, __nv_bfloat16* __restrict__ Whi,
                                __nv_bfloat16* __restrict__ Wlo, float* __restrict__ bsel, int Kd)
{
    int idx = blockIdx.x * blockDim.x + threadIdx.x;
    int total = G3 * Kd;
    if (idx < total) {
        int j = idx / Kd;
        int c = idx - j * Kd;
        int srcRow = j + ((j >= 256) ? 256 : 0);
        float v = W[srcRow * Kd + c];
        split1(v, Whi[idx], Wlo[idx]);
    }
    if (idx < G3) {
        int srcRow = idx + ((idx >= 256) ? 256 : 0);
        bsel[idx] = bih[srcRow] + bhh[srcRow];
    }
}

__device__ __forceinline__ float sigm(float x) { return 1.f / (1.f + expf(-x)); }

__global__ void lstm_gate_split(const float* __restrict__ gates, const float* __restrict__ bsel,
                                float* __restrict__ outF, __nv_bfloat16* __restrict__ hi,
                                __nv_bfloat16* __restrict__ lo, int M)
{
    int idx = blockIdx.x * blockDim.x + threadIdx.x;
    if (idx >= M * H_) return;
    int m = idx >> 8;
    int j = idx & 255;
    const float* gr = gates + (size_t)m * G3;
    float gi = gr[j]       + bsel[j];
    float gg = gr[256 + j] + bsel[256 + j];
    float go = gr[512 + j] + bsel[512 + j];
    float c = sigm(gi) * tanhf(gg);
    float v = sigm(go) * tanhf(c);
    if (outF) outF[idx] = v;
    split1(v, hi[idx], lo[idx]);
}

__global__ void reduce_bias_act(const float* __restrict__ part, int S, int MN, int N,
                                const float* __restrict__ bias, float* __restrict__ out, int relu)
{
    int idx = blockIdx.x * blockDim.x + threadIdx.x;
    if (idx >= MN) return;
    float s = 0.f;
    for (int i = 0; i < S; i++) s += part[(size_t)i * MN + idx];
    s += bias[idx % N];
    if (relu) s = fmaxf(s, 0.f);
    out[idx] = s;
}

// ---------------- fp32 SGEMM (small fc layers) ----------------
__global__ void __launch_bounds__(256, 2)
sgemm_nt(const float* __restrict__ A, const float* __restrict__ B,
         float* __restrict__ C, int M, int N, int K, int kSlice)
{
    constexpr int BM = 128, BN = 128, BK = 8;
    __shared__ float As[BK][BM];
    __shared__ float Bs[BK][BN];
    const int tid = threadIdx.x;
    const int mBase = blockIdx.y * BM;
    const int nBase = blockIdx.x * BN;
    const int z = blockIdx.z;
    const int kBeg = z * kSlice;
    const int kEnd = kBeg + kSlice;
    const int lr = tid >> 1;
    const int lc = (tid & 1) * 4;
    const int tr = (tid >> 4) * 8;
    const int tc = (tid & 15) * 8;
    float acc[8][8];
#pragma unroll
    for (int i = 0; i < 8; i++)
#pragma unroll
        for (int j = 0; j < 8; j++) acc[i][j] = 0.f;
    const float* Aptr = A + (size_t)(mBase + lr) * K;
    const bool bvalid = (nBase + lr) < N;
    const float* Bptr = B + (bvalid ? (size_t)(nBase + lr) * K : 0);
    for (int k0 = kBeg; k0 < kEnd; k0 += BK) {
        float4 a4 = *reinterpret_cast<const float4*>(Aptr + k0 + lc);
        float4 b4 = make_float4(0.f, 0.f, 0.f, 0.f);
        if (bvalid) b4 = *reinterpret_cast<const float4*>(Bptr + k0 + lc);
        As[lc + 0][lr] = a4.x; As[lc + 1][lr] = a4.y;
        As[lc + 2][lr] = a4.z; As[lc + 3][lr] = a4.w;
        Bs[lc + 0][lr] = b4.x; Bs[lc + 1][lr] = b4.y;
        Bs[lc + 2][lr] = b4.z; Bs[lc + 3][lr] = b4.w;
        __syncthreads();
#pragma unroll
        for (int kk = 0; kk < BK; kk++) {
            float rm[8], rn[8];
#pragma unroll
            for (int i = 0; i < 8; i++) rm[i] = As[kk][tr + i];
#pragma unroll
            for (int j = 0; j < 8; j++) rn[j] = Bs[kk][tc + j];
#pragma unroll
            for (int i = 0; i < 8; i++)
#pragma unroll
                for (int j = 0; j < 8; j++) acc[i][j] = fmaf(rm[i], rn[j], acc[i][j]);
        }
        __syncthreads();
    }
    float* Cp = C + (size_t)z * M * N;
#pragma unroll
    for (int i = 0; i < 8; i++) {
        const size_t rowOff = (size_t)(mBase + tr + i) * N;
#pragma unroll
        for (int j = 0; j < 8; j++) {
            int col = nBase + tc + j;
            if (col < N) Cp[rowOff + col] = acc[i][j];
        }
    }
}

__global__ void fc3_kernel(const float* __restrict__ x, const float* __restrict__ W,
                           const float* __restrict__ b, float* __restrict__ out)
{
    int idx = blockIdx.x * blockDim.x + threadIdx.x;
    if (idx >= B_ * C3_) return;
    int m = idx / C3_;
    int n = idx - m * C3_;
    const float* xr = x + m * C2_;
    const float* wr = W + n * C2_;
    float s = 0.f;
#pragma unroll 4
    for (int k = 0; k < C2_; k++) s = fmaf(xr[k], wr[k], s);
    out[idx] = s + b[n];
}

// ---------------- launch ----------------
extern "C" void kernel_launch(void* const* d_in, const int* in_sizes, int n_in,
                              void* d_out_v, int out_size)
{
    const float* x     = (const float*)d_in[0];
    const float* W_ih0 = (const float*)d_in[1];
    const float* b_ih0 = (const float*)d_in[2];
    const float* b_hh0 = (const float*)d_in[3];
    const float* W_ih1 = (const float*)d_in[4];
    const float* b_ih1 = (const float*)d_in[5];
    const float* b_hh1 = (const float*)d_in[6];
    const float* fc1_w = (const float*)d_in[7];
    const float* fc1_b = (const float*)d_in[8];
    const float* fc2_w = (const float*)d_in[9];
    const float* fc2_b = (const float*)d_in[10];
    const float* fc3_w = (const float*)d_in[11];
    const float* fc3_b = (const float*)d_in[12];
    const float* fc4_w = (const float*)d_in[13];
    const float* fc4_b = (const float*)d_in[14];
    const float* fc5_w = (const float*)d_in[15];
    const float* fc5_b = (const float*)d_in[16];
    float* d_out = (float*)d_out_v;

    cudaFuncSetAttribute(hm_gemm, cudaFuncAttributeMaxDynamicSharedMemorySize, HM_SMEM);

    __nv_bfloat16 *w0h, *w0l, *w1h, *w1l, *xh, *xl, *h0h, *h0l, *fh, *fl, *f1h, *f1l, *f4h, *f4l;
    float *bsel0, *bsel1, *gates, *part, *c1, *c2, *r;
    cudaGetSymbolAddress((void**)&w0h, g_w0h);   cudaGetSymbolAddress((void**)&w0l, g_w0l);
    cudaGetSymbolAddress((void**)&w1h, g_w1h);   cudaGetSymbolAddress((void**)&w1l, g_w1l);
    cudaGetSymbolAddress((void**)&bsel0, g_bsel0); cudaGetSymbolAddress((void**)&bsel1, g_bsel1);
    cudaGetSymbolAddress((void**)&xh, g_xh);     cudaGetSymbolAddress((void**)&xl, g_xl);
    cudaGetSymbolAddress((void**)&h0h, g_h0h);   cudaGetSymbolAddress((void**)&h0l, g_h0l);
    cudaGetSymbolAddress((void**)&fh, g_fh);     cudaGetSymbolAddress((void**)&fl, g_fl);
    cudaGetSymbolAddress((void**)&f1h, g_fc1h);  cudaGetSymbolAddress((void**)&f1l, g_fc1l);
    cudaGetSymbolAddress((void**)&f4h, g_fc4h);  cudaGetSymbolAddress((void**)&f4l, g_fc4l);
    cudaGetSymbolAddress((void**)&gates, g_gates);
    cudaGetSymbolAddress((void**)&part, g_part);
    cudaGetSymbolAddress((void**)&c1, g_c1);
    cudaGetSymbolAddress((void**)&c2, g_c2);
    cudaGetSymbolAddress((void**)&r, g_r);

    // conversions
    make_wsel_split<<<(G3 * D_ + 255) / 256, 256>>>(W_ih0, b_ih0, b_hh0, w0h, w0l, bsel0, D_);
    make_wsel_split<<<(G3 * H_ + 255) / 256, 256>>>(W_ih1, b_ih1, b_hh1, w1h, w1l, bsel1, H_);
    {
        size_t n = (size_t)BT * D_;
        split_f32<<<(unsigned)((n / 4 + 255) / 256), 256>>>(x, xh, xl, n);
        n = (size_t)C1_ * HT;
        split_f32<<<(unsigned)((n / 4 + 255) / 256), 256>>>(fc1_w, f1h, f1l, n);
        split_f32<<<(unsigned)((n / 4 + 255) / 256), 256>>>(fc4_w, f4h, f4l, n);
    }

    // LSTM layer 0: gates = x[BT,64] @ Wsel0[768,64]^T
    hm_gemm<<<dim3(G3 / 128, BT / 128, 1), 256, HM_SMEM>>>(xh, xl, w0h, w0l, gates, BT, G3, D_, D_);
    lstm_gate_split<<<(BT * H_ + 255) / 256, 256>>>(gates, bsel0, nullptr, h0h, h0l, BT);

    // LSTM layer 1: gates = h0[BT,256] @ Wsel1[768,256]^T -> out_total + flat split
    hm_gemm<<<dim3(G3 / 128, BT / 128, 1), 256, HM_SMEM>>>(h0h, h0l, w1h, w1l, gates, BT, G3, H_, H_);
    lstm_gate_split<<<(BT * H_ + 255) / 256, 256>>>(gates, bsel1, d_out + OUT_TOTAL_OFF, fh, fl, BT);

    // fc1: [512,51200] x [1024,51200]^T, split-K=16
    hm_gemm<<<dim3(C1_ / 128, B_ / 128, 16), 256, HM_SMEM>>>(fh, fl, f1h, f1l, part, B_, C1_, HT, HT / 16);
    reduce_bias_act<<<(B_ * C1_ + 255) / 256, 256>>>(part, 16, B_ * C1_, C1_, fc1_b, c1, 1);

    // fc2 (fp32 path) + relu
    sgemm_nt<<<dim3(C2_ / 128, B_ / 128, 4), 256>>>(c1, fc2_w, part, B_, C2_, C1_, C1_ / 4);
    reduce_bias_act<<<(B_ * C2_ + 255) / 256, 256>>>(part, 4, B_ * C2_, C2_, fc2_b, c2, 1);

    // fc3 -> class output
    fc3_kernel<<<(B_ * C3_ + 255) / 256, 256>>>(c2, fc3_w, fc3_b, d_out + OUT_CLASS_OFF);

    // fc4: split-K=16
    hm_gemm<<<dim3(R1_ / 128, B_ / 128, 16), 256, HM_SMEM>>>(fh, fl, f4h, f4l, part, B_, R1_, HT, HT / 16);
    reduce_bias_act<<<(B_ * R1_ + 255) / 256, 256>>>(part, 16, B_ * R1_, R1_, fc4_b, r, 1);

    // fc5 (fp32 path, N=200 ragged) -> regression output
    sgemm_nt<<<dim3((T_ + 127) / 128, B_ / 128, 4), 256>>>(r, fc5_w, part, B_, T_, R1_, R1_ / 4);
    reduce_bias_act<<<(B_ * T_ + 255) / 256, 256>>>(part, 4, B_ * T_, T_, fc5_b,
                                                    d_out + OUT_REG_OFF, 0);
}

// round 6
// speedup vs baseline: 2.6550x; 1.7714x over previous
#include <cuda_runtime.h>
#include <cuda_bf16.h>
#include <math.h>
#include <stdint.h>

// ---------------- problem constants ----------------
constexpr int B_  = 512;
constexpr int T_  = 200;
constexpr int D_  = 64;
constexpr int H_  = 256;
constexpr int BT  = B_ * T_;        // 102400 rows
constexpr int HT  = H_ * T_;        // 51200 flat dim
constexpr int C1_ = 1024;
constexpr int C2_ = 256;
constexpr int C3_ = 10;
constexpr int R1_ = 1024;
constexpr int G3  = 768;            // packed gates i,g,o (forget gate dead, c0=0)

constexpr size_t OUT_TOTAL_OFF = 0;
constexpr size_t OUT_CLASS_OFF = (size_t)BT * H_;
constexpr size_t OUT_REG_OFF   = OUT_CLASS_OFF + (size_t)B_ * C3_;

// ---------------- device scratch ----------------
__device__ float g_wsel0[G3 * D_];          // packed i,g,o rows fp32
__device__ float g_wsel1[G3 * H_];
__device__ float g_bsel0[G3], g_bsel1[G3];
__device__ float g_h0[(size_t)BT * H_];     // 105 MB fp32
__device__ float g_part[16 * 512 * 1024];   // split-K partials
__device__ float g_c1[B_ * C1_];
__device__ float g_c2[B_ * C2_];
__device__ float g_r [B_ * R1_];

// ---------------- PTX helpers (sm_80-compatible only) ----------------
__device__ __forceinline__ uint32_t smem_u32(const void* p) {
    uint32_t a;
    asm("{ .reg .u64 t; cvta.to.shared.u64 t, %1; cvt.u32.u64 %0, t; }" : "=r"(a) : "l"(p));
    return a;
}
__device__ __forceinline__ void ldsm_x4(uint32_t* r, uint32_t addr) {
    asm volatile("ldmatrix.sync.aligned.m8n8.x4.shared.b16 {%0,%1,%2,%3}, [%4];"
                 : "=r"(r[0]), "=r"(r[1]), "=r"(r[2]), "=r"(r[3]) : "r"(addr));
}
__device__ __forceinline__ void ldsm_x2(uint32_t* r, uint32_t addr) {
    asm volatile("ldmatrix.sync.aligned.m8n8.x2.shared.b16 {%0,%1}, [%2];"
                 : "=r"(r[0]), "=r"(r[1]) : "r"(addr));
}
__device__ __forceinline__ void mma_bf16(float* c, const uint32_t* a, const uint32_t* b) {
    asm volatile("mma.sync.aligned.m16n8k16.row.col.f32.bf16.bf16.f32 "
                 "{%0,%1,%2,%3}, {%4,%5,%6,%7}, {%8,%9}, {%0,%1,%2,%3};"
                 : "+f"(c[0]), "+f"(c[1]), "+f"(c[2]), "+f"(c[3])
                 : "r"(a[0]), "r"(a[1]), "r"(a[2]), "r"(a[3]), "r"(b[0]), "r"(b[1]));
}
__device__ __forceinline__ uint32_t pack_bf2(float a, float b) {
    __nv_bfloat162 t = __floats2bfloat162_rn(a, b);
    return *reinterpret_cast<uint32_t*>(&t);
}
__device__ __forceinline__ float bf_hi(float v) {
    __nv_bfloat16 h = __float2bfloat16(v);
    return __bfloat162float(h);
}
__device__ __forceinline__ float sigm(float x) { return 1.f / (1.f + expf(-x)); }

// ---------------- hi/lo-split HMMA GEMM (fp32 in, fp32 out) ----------------
// Standard mode: C[z][M,N] partial = A[M,K] * B[N,K]^T over k-slice z.
// Gate mode: for gate g in {i,g,o}: acc_g = A * Wsel[g*256+n, :]^T + bias,
//            h = sigm(i)*... composed via smem stash; writes h[M,256] fp32.
// Tile 128x128x64, 512 threads, warp grid 4x4, warp tile 32x32.
constexpr int HS_ROWB  = 144;               // 64 bf16 + 8 pad, bytes
constexpr int HS_TILE  = 128 * HS_ROWB;     // 18432
constexpr int HS_OPER  = 4 * HS_TILE;       // 73728
constexpr int HS_STASH = 128 * 132 * 4;     // 67584 (128x128 fp32, 4-float row pad)
constexpr int HS_SMEM_GATE = HS_OPER + HS_STASH;

__global__ void __launch_bounds__(512, 1)
hs_gemm(const float* __restrict__ A, const float* __restrict__ Bw,
        float* __restrict__ C, const float* __restrict__ bias,
        int M, int N, int K, int kSlice, int gateMode)
{
    extern __shared__ __align__(128) char smem[];
    char* pAhi = smem;
    char* pAlo = smem + HS_TILE;
    char* pBhi = smem + 2 * HS_TILE;
    char* pBlo = smem + 3 * HS_TILE;
    float* stash = reinterpret_cast<float*>(smem + HS_OPER);
    const uint32_t sAhi = smem_u32(pAhi);
    const uint32_t sAlo = sAhi + HS_TILE;
    const uint32_t sBhi = sAhi + 2 * HS_TILE;
    const uint32_t sBlo = sAhi + 3 * HS_TILE;

    const int tid  = threadIdx.x;
    const int lane = tid & 31;
    const int warp = tid >> 5;
    const int wm   = warp >> 2;              // 0..3
    const int wn   = warp & 3;               // 0..3
    const int mBase = blockIdx.y * 128;
    const int nBase = blockIdx.x * 128;
    const int z     = gateMode ? 0 : blockIdx.z;
    const int kBeg  = z * kSlice;
    const int NC    = kSlice >> 6;

    const int aRow = (lane & 7) + ((lane >> 3) & 1) * 8;
    const int aCol = (lane >> 4) * 8;
    const int bRow = lane & 7;
    const int bCol = ((lane >> 3) & 1) * 8;

    // loader: 2048 float4 per operand tile, 4 per thread
    int lr[4], lc4[4];
#pragma unroll
    for (int t = 0; t < 4; t++) {
        int idx = tid + t * 512;
        lr[t]  = idx >> 4;        // 0..127
        lc4[t] = idx & 15;        // float4 unit within 64-col row
    }

    const int nGates = gateMode ? 3 : 1;

    for (int g = 0; g < nGates; g++) {
        const int rowOff = gateMode ? (g * 256 + nBase) : nBase;

        float acc[2][4][4];
#pragma unroll
        for (int mi = 0; mi < 2; mi++)
#pragma unroll
            for (int ni = 0; ni < 4; ni++)
#pragma unroll
                for (int q = 0; q < 4; q++) acc[mi][ni][q] = 0.f;

        float4 aR[4], bR[4];
        // prefetch chunk 0
        {
            int kk = kBeg;
#pragma unroll
            for (int t = 0; t < 4; t++) {
                aR[t] = *reinterpret_cast<const float4*>(A  + (size_t)(mBase + lr[t]) * K + kk + lc4[t] * 4);
                bR[t] = *reinterpret_cast<const float4*>(Bw + (size_t)(rowOff + lr[t]) * K + kk + lc4[t] * 4);
            }
        }

        for (int c = 0; c < NC; c++) {
            __syncthreads();   // prior MMA done before overwriting smem
            // STS: split fp32 -> hi/lo bf16
#pragma unroll
            for (int t = 0; t < 4; t++) {
                int off = lr[t] * HS_ROWB + lc4[t] * 8;
                float4 v = aR[t];
                float hx = bf_hi(v.x), hy = bf_hi(v.y), hz = bf_hi(v.z), hw = bf_hi(v.w);
                *reinterpret_cast<uint2*>(pAhi + off) =
                    make_uint2(pack_bf2(hx, hy), pack_bf2(hz, hw));
                *reinterpret_cast<uint2*>(pAlo + off) =
                    make_uint2(pack_bf2(v.x - hx, v.y - hy), pack_bf2(v.z - hz, v.w - hw));
                v = bR[t];
                hx = bf_hi(v.x); hy = bf_hi(v.y); hz = bf_hi(v.z); hw = bf_hi(v.w);
                *reinterpret_cast<uint2*>(pBhi + off) =
                    make_uint2(pack_bf2(hx, hy), pack_bf2(hz, hw));
                *reinterpret_cast<uint2*>(pBlo + off) =
                    make_uint2(pack_bf2(v.x - hx, v.y - hy), pack_bf2(v.z - hz, v.w - hw));
            }
            __syncthreads();
            if (c + 1 < NC) {
                int kk = kBeg + (c + 1) * 64;
#pragma unroll
                for (int t = 0; t < 4; t++) {
                    aR[t] = *reinterpret_cast<const float4*>(A  + (size_t)(mBase + lr[t]) * K + kk + lc4[t] * 4);
                    bR[t] = *reinterpret_cast<const float4*>(Bw + (size_t)(rowOff + lr[t]) * K + kk + lc4[t] * 4);
                }
            }
            // MMA: 3 sub-passes per chunk on shared fragments
#pragma unroll
            for (int ks = 0; ks < 4; ks++) {
                uint32_t ah[2][4], al[2][4], bh[4][2], bl[4][2];
#pragma unroll
                for (int mi = 0; mi < 2; mi++) {
                    uint32_t ro = (wm * 32 + mi * 16 + aRow) * HS_ROWB + (ks * 16 + aCol) * 2;
                    ldsm_x4(ah[mi], sAhi + ro);
                    ldsm_x4(al[mi], sAlo + ro);
                }
#pragma unroll
                for (int ni = 0; ni < 4; ni++) {
                    uint32_t ro = (wn * 32 + ni * 8 + bRow) * HS_ROWB + (ks * 16 + bCol) * 2;
                    ldsm_x2(bh[ni], sBhi + ro);
                    ldsm_x2(bl[ni], sBlo + ro);
                }
#pragma unroll
                for (int mi = 0; mi < 2; mi++)
#pragma unroll
                    for (int ni = 0; ni < 4; ni++) {
                        mma_bf16(acc[mi][ni], ah[mi], bh[ni]);
                        mma_bf16(acc[mi][ni], ah[mi], bl[ni]);
                        mma_bf16(acc[mi][ni], al[mi], bh[ni]);
                    }
            }
        }

        // ---- epilogue ----
        if (!gateMode) {
            float* Cp = C + (size_t)z * M * N;
#pragma unroll
            for (int mi = 0; mi < 2; mi++) {
                int r0 = mBase + wm * 32 + mi * 16 + (lane >> 2);
#pragma unroll
                for (int ni = 0; ni < 4; ni++) {
                    int col = nBase + wn * 32 + ni * 8 + (lane & 3) * 2;
                    *reinterpret_cast<float2*>(&Cp[(size_t)r0 * N + col]) =
                        make_float2(acc[mi][ni][0], acc[mi][ni][1]);
                    *reinterpret_cast<float2*>(&Cp[(size_t)(r0 + 8) * N + col]) =
                        make_float2(acc[mi][ni][2], acc[mi][ni][3]);
                }
            }
        } else {
#pragma unroll
            for (int mi = 0; mi < 2; mi++)
#pragma unroll
                for (int ni = 0; ni < 4; ni++)
#pragma unroll
                    for (int q = 0; q < 4; q++) {
                        int rl = wm * 32 + mi * 16 + (lane >> 2) + ((q >= 2) ? 8 : 0);
                        int cl = wn * 32 + ni * 8 + (lane & 3) * 2 + (q & 1);
                        float v = acc[mi][ni][q] + bias[rowOff + cl];
                        int si = rl * 132 + cl;
                        if (g == 0)      stash[si] = sigm(v);
                        else if (g == 1) stash[si] *= tanhf(v);
                        else {
                            float h = sigm(v) * tanhf(stash[si]);
                            C[(size_t)(mBase + rl) * H_ + nBase + cl] = h;
                        }
                    }
        }
    }
}

// ---------------- small kernels ----------------
// pack gate rows {i, g, o} of W_ih into fp32 [768,Kd]; bsel = b_ih + b_hh
__global__ void make_wsel(const float* __restrict__ W, const float* __restrict__ bih,
                          const float* __restrict__ bhh, float* __restrict__ Wsel,
                          float* __restrict__ bsel, int Kd)
{
    int idx = blockIdx.x * blockDim.x + threadIdx.x;
    int total = G3 * Kd;
    if (idx < total) {
        int j = idx / Kd;
        int c = idx - j * Kd;
        int src = j + ((j >= 256) ? 256 : 0);
        Wsel[idx] = W[src * Kd + c];
    }
    if (idx < G3) {
        int src = idx + ((idx >= 256) ? 256 : 0);
        bsel[idx] = bih[src] + bhh[src];
    }
}

__global__ void reduce_bias_act(const float* __restrict__ part, int S, int MN, int N,
                                const float* __restrict__ bias, float* __restrict__ out, int relu)
{
    int idx = blockIdx.x * blockDim.x + threadIdx.x;
    if (idx >= MN) return;
    float s = 0.f;
    for (int i = 0; i < S; i++) s += part[(size_t)i * MN + idx];
    s += bias[idx % N];
    if (relu) s = fmaxf(s, 0.f);
    out[idx] = s;
}

// ---------------- fp32 SGEMM (small fc layers) ----------------
__global__ void __launch_bounds__(256, 2)
sgemm_nt(const float* __restrict__ A, const float* __restrict__ B,
         float* __restrict__ C, int M, int N, int K, int kSlice)
{
    constexpr int BM = 128, BN = 128, BK = 8;
    __shared__ float As[BK][BM];
    __shared__ float Bs[BK][BN];
    const int tid = threadIdx.x;
    const int mBase = blockIdx.y * BM;
    const int nBase = blockIdx.x * BN;
    const int z = blockIdx.z;
    const int kBeg = z * kSlice;
    const int kEnd = kBeg + kSlice;
    const int lr = tid >> 1;
    const int lc = (tid & 1) * 4;
    const int tr = (tid >> 4) * 8;
    const int tc = (tid & 15) * 8;
    float acc[8][8];
#pragma unroll
    for (int i = 0; i < 8; i++)
#pragma unroll
        for (int j = 0; j < 8; j++) acc[i][j] = 0.f;
    const float* Aptr = A + (size_t)(mBase + lr) * K;
    const bool bvalid = (nBase + lr) < N;
    const float* Bptr = B + (bvalid ? (size_t)(nBase + lr) * K : 0);
    for (int k0 = kBeg; k0 < kEnd; k0 += BK) {
        float4 a4 = *reinterpret_cast<const float4*>(Aptr + k0 + lc);
        float4 b4 = make_float4(0.f, 0.f, 0.f, 0.f);
        if (bvalid) b4 = *reinterpret_cast<const float4*>(Bptr + k0 + lc);
        As[lc + 0][lr] = a4.x; As[lc + 1][lr] = a4.y;
        As[lc + 2][lr] = a4.z; As[lc + 3][lr] = a4.w;
        Bs[lc + 0][lr] = b4.x; Bs[lc + 1][lr] = b4.y;
        Bs[lc + 2][lr] = b4.z; Bs[lc + 3][lr] = b4.w;
        __syncthreads();
#pragma unroll
        for (int kk = 0; kk < BK; kk++) {
            float rm[8], rn[8];
#pragma unroll
            for (int i = 0; i < 8; i++) rm[i] = As[kk][tr + i];
#pragma unroll
            for (int j = 0; j < 8; j++) rn[j] = Bs[kk][tc + j];
#pragma unroll
            for (int i = 0; i < 8; i++)
#pragma unroll
                for (int j = 0; j < 8; j++) acc[i][j] = fmaf(rm[i], rn[j], acc[i][j]);
        }
        __syncthreads();
    }
    float* Cp = C + (size_t)z * M * N;
#pragma unroll
    for (int i = 0; i < 8; i++) {
        const size_t rowOff = (size_t)(mBase + tr + i) * N;
#pragma unroll
        for (int j = 0; j < 8; j++) {
            int col = nBase + tc + j;
            if (col < N) Cp[rowOff + col] = acc[i][j];
        }
    }
}

__global__ void fc3_kernel(const float* __restrict__ x, const float* __restrict__ W,
                           const float* __restrict__ b, float* __restrict__ out)
{
    int idx = blockIdx.x * blockDim.x + threadIdx.x;
    if (idx >= B_ * C3_) return;
    int m = idx / C3_;
    int n = idx - m * C3_;
    const float* xr = x + m * C2_;
    const float* wr = W + n * C2_;
    float s = 0.f;
#pragma unroll 4
    for (int k = 0; k < C2_; k++) s = fmaf(xr[k], wr[k], s);
    out[idx] = s + b[n];
}

// ---------------- launch ----------------
extern "C" void kernel_launch(void* const* d_in, const int* in_sizes, int n_in,
                              void* d_out_v, int out_size)
{
    const float* x     = (const float*)d_in[0];
    const float* W_ih0 = (const float*)d_in[1];
    const float* b_ih0 = (const float*)d_in[2];
    const float* b_hh0 = (const float*)d_in[3];
    const float* W_ih1 = (const float*)d_in[4];
    const float* b_ih1 = (const float*)d_in[5];
    const float* b_hh1 = (const float*)d_in[6];
    const float* fc1_w = (const float*)d_in[7];
    const float* fc1_b = (const float*)d_in[8];
    const float* fc2_w = (const float*)d_in[9];
    const float* fc2_b = (const float*)d_in[10];
    const float* fc3_w = (const float*)d_in[11];
    const float* fc3_b = (const float*)d_in[12];
    const float* fc4_w = (const float*)d_in[13];
    const float* fc4_b = (const float*)d_in[14];
    const float* fc5_w = (const float*)d_in[15];
    const float* fc5_b = (const float*)d_in[16];
    float* d_out = (float*)d_out_v;

    cudaFuncSetAttribute(hs_gemm, cudaFuncAttributeMaxDynamicSharedMemorySize, HS_SMEM_GATE);

    float *wsel0, *wsel1, *bsel0, *bsel1, *h0, *part, *c1, *c2, *r;
    cudaGetSymbolAddress((void**)&wsel0, g_wsel0);
    cudaGetSymbolAddress((void**)&wsel1, g_wsel1);
    cudaGetSymbolAddress((void**)&bsel0, g_bsel0);
    cudaGetSymbolAddress((void**)&bsel1, g_bsel1);
    cudaGetSymbolAddress((void**)&h0,    g_h0);
    cudaGetSymbolAddress((void**)&part,  g_part);
    cudaGetSymbolAddress((void**)&c1,    g_c1);
    cudaGetSymbolAddress((void**)&c2,    g_c2);
    cudaGetSymbolAddress((void**)&r,     g_r);

    // pack gate weights (fp32, skip forget gate)
    make_wsel<<<(G3 * D_ + 255) / 256, 256>>>(W_ih0, b_ih0, b_hh0, wsel0, bsel0, D_);
    make_wsel<<<(G3 * H_ + 255) / 256, 256>>>(W_ih1, b_ih1, b_hh1, wsel1, bsel1, H_);

    // LSTM layer 0 (gate mode): h0 = lstm(x @ Wsel0^T + bsel0)
    hs_gemm<<<dim3(2, BT / 128, 1), 512, HS_SMEM_GATE>>>(
        x, wsel0, h0, bsel0, BT, H_, D_, D_, 1);

    // LSTM layer 1 (gate mode): out_total = lstm(h0 @ Wsel1^T + bsel1) -> d_out fp32
    hs_gemm<<<dim3(2, BT / 128, 1), 512, HS_SMEM_GATE>>>(
        h0, wsel1, d_out + OUT_TOTAL_OFF, bsel1, BT, H_, H_, H_, 1);

    const float* flat = d_out + OUT_TOTAL_OFF;  // [512, 51200] fp32

    // fc1 (split-K=16) + relu
    hs_gemm<<<dim3(C1_ / 128, B_ / 128, 16), 512, HS_OPER>>>(
        flat, fc1_w, part, nullptr, B_, C1_, HT, HT / 16, 0);
    reduce_bias_act<<<(B_ * C1_ + 255) / 256, 256>>>(part, 16, B_ * C1_, C1_, fc1_b, c1, 1);

    // fc2 (fp32 path) + relu
    sgemm_nt<<<dim3(C2_ / 128, B_ / 128, 4), 256>>>(c1, fc2_w, part, B_, C2_, C1_, C1_ / 4);
    reduce_bias_act<<<(B_ * C2_ + 255) / 256, 256>>>(part, 4, B_ * C2_, C2_, fc2_b, c2, 1);

    // fc3 -> class output
    fc3_kernel<<<(B_ * C3_ + 255) / 256, 256>>>(c2, fc3_w, fc3_b, d_out + OUT_CLASS_OFF);

    // fc4 (split-K=16) + relu
    hs_gemm<<<dim3(R1_ / 128, B_ / 128, 16), 512, HS_OPER>>>(
        flat, fc4_w, part, nullptr, B_, R1_, HT, HT / 16, 0);
    reduce_bias_act<<<(B_ * R1_ + 255) / 256, 256>>>(part, 16, B_ * R1_, R1_, fc4_b, r, 1);

    // fc5 (fp32 path, N=200 ragged) -> regression output
    sgemm_nt<<<dim3((T_ + 127) / 128, B_ / 128, 4), 256>>>(r, fc5_w, part, B_, T_, R1_, R1_ / 4);
    reduce_bias_act<<<(B_ * T_ + 255) / 256, 256>>>(part, 4, B_ * T_, T_, fc5_b,
                                                    d_out + OUT_REG_OFF, 0);
}